// round 14
// baseline (speedup 1.0000x reference)
#include <cuda_runtime.h>
#include <cuda_fp16.h>
#include <math.h>

#define N_NODES 50000
#define FEAT    120
#define TOPO    8
#define KIN     128   // FEAT + TOPO
#define H1D1    64    // 8 heads * 8 dim
#define NH      8
#define D1      8
#define C       40
#define NEG     0.2f
#define EMAX_TOT (800000 + N_NODES)
#define NB_SCAN ((N_NODES + 1023) / 1024)

// ---- scratch (device globals; no allocation allowed) ----
__device__ __align__(16) __half g_h1h[N_NODES * H1D1];   // layer-1 features, fp16
__device__ float g_als1[N_NODES * NH];
__device__ float g_ald1[N_NODES * NH];
__device__ __align__(16) float g_h2  [N_NODES * H1D1];
__device__ __align__(16) __half g_g2h[N_NODES * C];      // layer-2 features, fp16
__device__ float g_als2[N_NODES];
__device__ float g_ald2[N_NODES];
// CSR scratch
__device__ struct CsrTmp {
    int cnt[N_NODES];
    unsigned long long state[NB_SCAN];
} g_tmp;
__device__ int g_off[N_NODES + 1];
__device__ unsigned short g_slot[EMAX_TOT];
__device__ unsigned short g_csr_src[EMAX_TOT];

__device__ __forceinline__ float lrelu(float x) { return x > 0.0f ? x : NEG * x; }

// ---- fork/join stream + events ----
static cudaStream_t s_side;
static cudaEvent_t  s_evFork, s_evJoin;
namespace {
struct StreamInit {
    StreamInit() {
        cudaStreamCreateWithFlags(&s_side, cudaStreamNonBlocking);
        cudaEventCreateWithFlags(&s_evFork, cudaEventDisableTiming);
        cudaEventCreateWithFlags(&s_evJoin, cudaEventDisableTiming);
    }
} s_streamInit;
}

// ======================= CSR build (R12 structure) =======================
__global__ void histK(const int* __restrict__ ei, int E, int Etot) {
    if (blockIdx.x == 0 && threadIdx.x < NB_SCAN) g_tmp.state[threadIdx.x] = 0ULL;
    int base = blockIdx.x * (blockDim.x * 4) + threadIdx.x;
#pragma unroll
    for (int r = 0; r < 4; ++r) {
        int e = base + r * blockDim.x;
        if (e < Etot) {
            int d = (e < E) ? ei[E + e] : (e - E);
            int old = atomicAdd(&g_tmp.cnt[d], 1);
            g_slot[e] = (unsigned short)old;
        }
    }
}

__global__ __launch_bounds__(1024) void scanK() {
    int b = blockIdx.x, t = threadIdx.x;
    int i = b * 1024 + t;
    int lane = t & 31, wid = t >> 5;
    int v = (i < N_NODES) ? g_tmp.cnt[i] : 0;
    if (i < N_NODES) g_tmp.cnt[i] = 0;
    int x = v;
#pragma unroll
    for (int off = 1; off < 32; off <<= 1) {
        int y = __shfl_up_sync(0xffffffffu, x, off);
        if (lane >= off) x += y;
    }
    __shared__ int wsum[32];
    if (lane == 31) wsum[wid] = x;
    __syncthreads();
    if (wid == 0) {
        int w = wsum[lane];
#pragma unroll
        for (int off = 1; off < 32; off <<= 1) {
            int y = __shfl_up_sync(0xffffffffu, w, off);
            if (lane >= off) w += y;
        }
        wsum[lane] = w;
    }
    __syncthreads();
    int blockIncl = x + (wid ? wsum[wid - 1] : 0);
    int total = wsum[31];

    __shared__ int s_prefix;
    if (t == 0) {
        if (b == 0) {
            atomicExch(&g_tmp.state[0], (2ULL << 32) | (unsigned)total);
            s_prefix = 0;
        } else {
            atomicExch(&g_tmp.state[b], (1ULL << 32) | (unsigned)total);
            int prefix = 0;
            for (int j = b - 1; j >= 0; --j) {
                unsigned long long st;
                do { st = atomicAdd(&g_tmp.state[j], 0ULL); } while ((st >> 32) == 0ULL);
                prefix += (int)(unsigned)st;
                if ((st >> 32) == 2ULL) break;
            }
            atomicExch(&g_tmp.state[b], (2ULL << 32) | (unsigned)(prefix + total));
            s_prefix = prefix;
        }
    }
    __syncthreads();
    if (i < N_NODES) g_off[i] = s_prefix + blockIncl - v;
    if (i == N_NODES - 1) g_off[N_NODES] = s_prefix + blockIncl;
}

__global__ void scatterK(const int* __restrict__ ei, int E, int Etot) {
    int base = blockIdx.x * (blockDim.x * 4) + threadIdx.x;
#pragma unroll
    for (int r = 0; r < 4; ++r) {
        int e = base + r * blockDim.x;
        if (e < Etot) {
            int s, d;
            if (e < E) { s = ei[e]; d = ei[E + e]; } else { s = d = e - E; }
            int pos = g_off[d] + (int)g_slot[e];
            g_csr_src[pos] = (unsigned short)s;
        }
    }
}

// ======================= Layer 1 GEMM (tiled, fp16 output) =======================
#define NT1 64
__global__ __launch_bounds__(256) void gemm1K(
        const float* __restrict__ x, const float* __restrict__ topo,
        const float* __restrict__ W1, const float* __restrict__ as1,
        const float* __restrict__ ad1) {
    __shared__ float xs[NT1][132];
    __shared__ float wt[64][132];
    __shared__ float hs[NT1][65];
    __shared__ float sas[64], sad[64];
    int t = threadIdx.x;
    int nbase = blockIdx.x * NT1;

    if (t < 64) { sas[t] = as1[t]; sad[t] = ad1[t]; }
    for (int i = t; i < 128 * 64; i += 256) {
        int k = i >> 6, c = i & 63;
        wt[c][k] = W1[i];
    }
    for (int i = t; i < NT1 * 128; i += 256) {
        int nl = i >> 7, k = i & 127;
        int n = nbase + nl;
        float v = 0.f;
        if (n < N_NODES) v = (k < FEAT) ? x[n * FEAT + k] : topo[n * TOPO + (k - FEAT)];
        xs[nl][k] = v;
    }
    __syncthreads();

    int cg = t & 15;
    int ng = t >> 4;
    float acc[4][4] = {};
#pragma unroll 4
    for (int k = 0; k < 128; k += 4) {
        float4 w0 = *(const float4*)&wt[cg][k];
        float4 w1v = *(const float4*)&wt[cg + 16][k];
        float4 w2v = *(const float4*)&wt[cg + 32][k];
        float4 w3v = *(const float4*)&wt[cg + 48][k];
#pragma unroll
        for (int u = 0; u < 4; ++u) {
            float4 xv = *(const float4*)&xs[ng * 4 + u][k];
            acc[u][0] += xv.x*w0.x + xv.y*w0.y + xv.z*w0.z + xv.w*w0.w;
            acc[u][1] += xv.x*w1v.x + xv.y*w1v.y + xv.z*w1v.z + xv.w*w1v.w;
            acc[u][2] += xv.x*w2v.x + xv.y*w2v.y + xv.z*w2v.z + xv.w*w2v.w;
            acc[u][3] += xv.x*w3v.x + xv.y*w3v.y + xv.z*w3v.z + xv.w*w3v.w;
        }
    }
#pragma unroll
    for (int u = 0; u < 4; ++u) {
        int nl = ng * 4 + u;
#pragma unroll
        for (int j = 0; j < 4; ++j)
            hs[nl][cg + j * 16] = acc[u][j];
    }
    __syncthreads();
#pragma unroll
    for (int rep = 0; rep < 2; ++rep) {
        int idx = t + rep * 256;
        int nl = idx >> 3, h = idx & 7;
        int n = nbase + nl;
        if (n < N_NODES) {
            float ts = 0.f, td = 0.f;
#pragma unroll
            for (int q = 0; q < 8; ++q) {
                float hv = hs[nl][h * 8 + q];
                ts = fmaf(hv, sas[h * 8 + q], ts);
                td = fmaf(hv, sad[h * 8 + q], td);
            }
            g_als1[n * NH + h] = ts;
            g_ald1[n * NH + h] = td;
        }
    }
    for (int i = t; i < NT1 * 8; i += 256) {
        int nl = i >> 3, q = i & 7;
        int n = nbase + nl;
        if (n < N_NODES) {
            __half2 hv[4];
#pragma unroll
            for (int j = 0; j < 4; ++j)
                hv[j] = __floats2half2_rn(hs[nl][q * 8 + j * 2], hs[nl][q * 8 + j * 2 + 1]);
            *(uint4*)(g_h1h + (size_t)n * H1D1 + q * 8) = *(uint4*)hv;
        }
    }
}

// ========== Layer 1 gather: group-owns-edge, 8-edge batched ==========
__global__ void gather1K(const float* __restrict__ b1) {
    int w = (blockIdx.x * blockDim.x + threadIdx.x) >> 5;
    if (w >= N_NODES) return;
    int lane = threadIdx.x & 31;
    int g = lane >> 3, l = lane & 7;
    int d = w;
    int beg = g_off[d], end = g_off[d + 1];
    float ald = g_ald1[d * NH + l];
    float acc[8] = {};
    float s = 0.f;
    int last = end - 1;

    for (int i = beg; i < end; i += 8) {
        int e0 = i + g, e1 = i + g + 4;
        bool v0 = e0 < end, v1 = e1 < end;
        int c0 = v0 ? e0 : last, c1 = v1 ? e1 : last;
        int s0 = (int)g_csr_src[c0];
        int s1 = (int)g_csr_src[c1];
        float a0 = g_als1[s0 * NH + l];
        float a1 = g_als1[s1 * NH + l];
        uint4 r0 = *(const uint4*)(g_h1h + (size_t)s0 * H1D1 + l * 8);
        uint4 r1 = *(const uint4*)(g_h1h + (size_t)s1 * H1D1 + l * 8);
        float p0 = v0 ? __expf(lrelu(a0 + ald)) : 0.f;
        float p1 = v1 ? __expf(lrelu(a1 + ald)) : 0.f;
        s += p0 + p1;
        float2 f;
        f = __half22float2(*(__half2*)&r0.x); acc[0] = fmaf(p0, f.x, acc[0]); acc[1] = fmaf(p0, f.y, acc[1]);
        f = __half22float2(*(__half2*)&r0.y); acc[2] = fmaf(p0, f.x, acc[2]); acc[3] = fmaf(p0, f.y, acc[3]);
        f = __half22float2(*(__half2*)&r0.z); acc[4] = fmaf(p0, f.x, acc[4]); acc[5] = fmaf(p0, f.y, acc[5]);
        f = __half22float2(*(__half2*)&r0.w); acc[6] = fmaf(p0, f.x, acc[6]); acc[7] = fmaf(p0, f.y, acc[7]);
        f = __half22float2(*(__half2*)&r1.x); acc[0] = fmaf(p1, f.x, acc[0]); acc[1] = fmaf(p1, f.y, acc[1]);
        f = __half22float2(*(__half2*)&r1.y); acc[2] = fmaf(p1, f.x, acc[2]); acc[3] = fmaf(p1, f.y, acc[3]);
        f = __half22float2(*(__half2*)&r1.z); acc[4] = fmaf(p1, f.x, acc[4]); acc[5] = fmaf(p1, f.y, acc[5]);
        f = __half22float2(*(__half2*)&r1.w); acc[6] = fmaf(p1, f.x, acc[6]); acc[7] = fmaf(p1, f.y, acc[7]);
    }
#pragma unroll
    for (int j = 0; j < 8; ++j) {
        acc[j] += __shfl_xor_sync(0xffffffffu, acc[j], 8);
        acc[j] += __shfl_xor_sync(0xffffffffu, acc[j], 16);
    }
    s += __shfl_xor_sync(0xffffffffu, s, 8);
    s += __shfl_xor_sync(0xffffffffu, s, 16);
    float inv = 1.f / s;
    if (g == 0) {
        float4 bv = *(const float4*)(b1 + l * 8);
        float4 v;
        v.x = acc[0] * inv + bv.x; v.y = acc[1] * inv + bv.y;
        v.z = acc[2] * inv + bv.z; v.w = acc[3] * inv + bv.w;
        v.x = v.x > 0.f ? v.x : expm1f(v.x); v.y = v.y > 0.f ? v.y : expm1f(v.y);
        v.z = v.z > 0.f ? v.z : expm1f(v.z); v.w = v.w > 0.f ? v.w : expm1f(v.w);
        *(float4*)(g_h2 + d * H1D1 + l * 8) = v;
    } else if (g == 1) {
        float4 bv = *(const float4*)(b1 + l * 8 + 4);
        float4 v;
        v.x = acc[4] * inv + bv.x; v.y = acc[5] * inv + bv.y;
        v.z = acc[6] * inv + bv.z; v.w = acc[7] * inv + bv.w;
        v.x = v.x > 0.f ? v.x : expm1f(v.x); v.y = v.y > 0.f ? v.y : expm1f(v.y);
        v.z = v.z > 0.f ? v.z : expm1f(v.z); v.w = v.w > 0.f ? v.w : expm1f(v.w);
        *(float4*)(g_h2 + d * H1D1 + l * 8 + 4) = v;
    }
}

// ===== Layer 2 GEMM: NT2=64 tile, 29KB smem -> ~6 blocks/SM (was 4 @46KB) =====
#define NT2 64
__global__ __launch_bounds__(320) void gemm2K(
        const float* __restrict__ W2, const float* __restrict__ as2,
        const float* __restrict__ ad2) {
    __shared__ float xs2[NT2][68];     // 17.4 KB
    __shared__ float ws2[64][44];      // 11.3 KB
    __shared__ float sas[40], sad[40];
    int t = threadIdx.x;
    int nbase = blockIdx.x * NT2;

    if (t < 40) { sas[t] = as2[t]; sad[t] = ad2[t]; }
    for (int i = t; i < 64 * C; i += 320) {
        int k = i / C, c = i - k * C;
        ws2[k][c] = W2[i];
    }
    for (int i = t; i < NT2 * 64; i += 320) {
        int nl = i >> 6, k = i & 63;
        int n = nbase + nl;
        xs2[nl][k] = (n < N_NODES) ? g_h2[n * H1D1 + k] : 0.f;
    }
    __syncthreads();

    int cg = t % 10;          // cols cg*4 .. cg*4+3
    int ng = t / 10;          // node pairs: nodes ng*2, ng*2+1
    float acc[2][4] = {};
#pragma unroll 4
    for (int k = 0; k < 64; k += 4) {
        float4 w0 = *(const float4*)&ws2[k + 0][cg * 4];
        float4 w1v = *(const float4*)&ws2[k + 1][cg * 4];
        float4 w2v = *(const float4*)&ws2[k + 2][cg * 4];
        float4 w3v = *(const float4*)&ws2[k + 3][cg * 4];
#pragma unroll
        for (int u = 0; u < 2; ++u) {
            float4 xv = *(const float4*)&xs2[ng * 2 + u][k];
            acc[u][0] += xv.x*w0.x + xv.y*w1v.x + xv.z*w2v.x + xv.w*w3v.x;
            acc[u][1] += xv.x*w0.y + xv.y*w1v.y + xv.z*w2v.y + xv.w*w3v.y;
            acc[u][2] += xv.x*w0.z + xv.y*w1v.z + xv.z*w2v.z + xv.w*w3v.z;
            acc[u][3] += xv.x*w0.w + xv.y*w1v.w + xv.z*w2v.w + xv.w*w3v.w;
        }
    }
    __syncthreads();           // done reading xs2; reuse rows for g2 values
#pragma unroll
    for (int u = 0; u < 2; ++u) {
        int nl = ng * 2 + u;
        int n = nbase + nl;
#pragma unroll
        for (int j = 0; j < 4; ++j) xs2[nl][cg * 4 + j] = acc[u][j];
        if (n < N_NODES) {
            union { __half2 h[2]; uint2 u2; } pk;
            pk.h[0] = __floats2half2_rn(acc[u][0], acc[u][1]);
            pk.h[1] = __floats2half2_rn(acc[u][2], acc[u][3]);
            *(uint2*)(g_g2h + (size_t)n * C + cg * 4) = pk.u2;
        }
    }
    __syncthreads();
    if (t < NT2) {
        int n = nbase + t;
        if (n < N_NODES) {
            float ts = 0.f, td = 0.f;
#pragma unroll 8
            for (int c = 0; c < C; ++c) {
                float gv = xs2[t][c];
                ts = fmaf(gv, sas[c], ts);
                td = fmaf(gv, sad[c], td);
            }
            g_als2[n] = ts;
            g_ald2[n] = td;
        }
    }
}

// ========== Layer 2 gather: group-owns-edge, fp16 g2 (lanes 0-4 carry 8 cols each) ==========
__global__ void gather2K(const float* __restrict__ b2, float* __restrict__ out) {
    int w = (blockIdx.x * blockDim.x + threadIdx.x) >> 5;
    if (w >= N_NODES) return;
    int lane = threadIdx.x & 31;
    int g = lane >> 3, l = lane & 7;
    int d = w;
    int beg = g_off[d], end = g_off[d + 1];
    float ald = g_ald2[d];
    float acc[8] = {};
    float s = 0.f;
    int last = end - 1;
    bool feat = (l < 5);
    int fcol = feat ? l * 8 : 0;

    for (int i = beg; i < end; i += 8) {
        int e0 = i + g, e1 = i + g + 4;
        bool v0 = e0 < end, v1 = e1 < end;
        int c0 = v0 ? e0 : last, c1 = v1 ? e1 : last;
        int s0 = (int)g_csr_src[c0];
        int s1 = (int)g_csr_src[c1];
        float a0 = g_als2[s0];
        float a1 = g_als2[s1];
        uint4 r0 = make_uint4(0, 0, 0, 0), r1 = make_uint4(0, 0, 0, 0);
        if (feat) {
            r0 = *(const uint4*)(g_g2h + (size_t)s0 * C + fcol);
            r1 = *(const uint4*)(g_g2h + (size_t)s1 * C + fcol);
        }
        float p0 = v0 ? __expf(lrelu(a0 + ald)) : 0.f;
        float p1 = v1 ? __expf(lrelu(a1 + ald)) : 0.f;
        s += p0 + p1;
        float2 f;
        f = __half22float2(*(__half2*)&r0.x); acc[0] = fmaf(p0, f.x, acc[0]); acc[1] = fmaf(p0, f.y, acc[1]);
        f = __half22float2(*(__half2*)&r0.y); acc[2] = fmaf(p0, f.x, acc[2]); acc[3] = fmaf(p0, f.y, acc[3]);
        f = __half22float2(*(__half2*)&r0.z); acc[4] = fmaf(p0, f.x, acc[4]); acc[5] = fmaf(p0, f.y, acc[5]);
        f = __half22float2(*(__half2*)&r0.w); acc[6] = fmaf(p0, f.x, acc[6]); acc[7] = fmaf(p0, f.y, acc[7]);
        f = __half22float2(*(__half2*)&r1.x); acc[0] = fmaf(p1, f.x, acc[0]); acc[1] = fmaf(p1, f.y, acc[1]);
        f = __half22float2(*(__half2*)&r1.y); acc[2] = fmaf(p1, f.x, acc[2]); acc[3] = fmaf(p1, f.y, acc[3]);
        f = __half22float2(*(__half2*)&r1.z); acc[4] = fmaf(p1, f.x, acc[4]); acc[5] = fmaf(p1, f.y, acc[5]);
        f = __half22float2(*(__half2*)&r1.w); acc[6] = fmaf(p1, f.x, acc[6]); acc[7] = fmaf(p1, f.y, acc[7]);
    }
#pragma unroll
    for (int j = 0; j < 8; ++j) {
        acc[j] += __shfl_xor_sync(0xffffffffu, acc[j], 8);
        acc[j] += __shfl_xor_sync(0xffffffffu, acc[j], 16);
    }
    s += __shfl_xor_sync(0xffffffffu, s, 8);
    s += __shfl_xor_sync(0xffffffffu, s, 16);
    float inv = 1.f / s;

    float v[8];
    float m = -INFINITY;
    if (feat) {
#pragma unroll
        for (int j = 0; j < 8; ++j) {
            v[j] = acc[j] * inv + b2[fcol + j];
            m = fmaxf(m, v[j]);
        }
    }
#pragma unroll
    for (int off = 1; off < 8; off <<= 1)
        m = fmaxf(m, __shfl_xor_sync(0xffffffffu, m, off));
    float es = 0.f;
    if (feat) {
#pragma unroll
        for (int j = 0; j < 8; ++j) es += expf(v[j] - m);
    }
#pragma unroll
    for (int off = 1; off < 8; off <<= 1)
        es += __shfl_xor_sync(0xffffffffu, es, off);
    float lse = logf(es) + m;
    if (g == 0 && feat) {
        float4 o0 = make_float4(v[0] - lse, v[1] - lse, v[2] - lse, v[3] - lse);
        float4 o1 = make_float4(v[4] - lse, v[5] - lse, v[6] - lse, v[7] - lse);
        *(float4*)(out + (size_t)d * C + fcol)     = o0;
        *(float4*)(out + (size_t)d * C + fcol + 4) = o1;
    }
}

extern "C" void kernel_launch(void* const* d_in, const int* in_sizes, int n_in,
                              void* d_out, int out_size) {
    const float* x    = (const float*)d_in[0];
    const float* topo = (const float*)d_in[1];
    const int*   ei   = (const int*)  d_in[2];
    const float* W1   = (const float*)d_in[3];
    const float* as1  = (const float*)d_in[4];
    const float* ad1  = (const float*)d_in[5];
    const float* b1   = (const float*)d_in[6];
    const float* W2   = (const float*)d_in[7];
    const float* as2  = (const float*)d_in[8];
    const float* ad2  = (const float*)d_in[9];
    const float* b2   = (const float*)d_in[10];
    float* out = (float*)d_out;

    int E    = in_sizes[2] / 2;
    int Etot = E + N_NODES;

    // fork: gemm1 runs concurrently with the CSR build
    cudaEventRecord(s_evFork, 0);
    cudaStreamWaitEvent(s_side, s_evFork, 0);
    gemm1K<<<(N_NODES + NT1 - 1) / NT1, 256, 0, s_side>>>(x, topo, W1, as1, ad1);
    cudaEventRecord(s_evJoin, s_side);

    // CSR build (no memset: cnt self-clears in scanK, state zeroed in histK)
    histK   <<<(Etot + 1023) / 1024, 256>>>(ei, E, Etot);
    scanK   <<<NB_SCAN, 1024>>>();
    scatterK<<<(Etot + 1023) / 1024, 256>>>(ei, E, Etot);

    // join, then the dependent chain
    cudaStreamWaitEvent(0, s_evJoin, 0);
    gather1K<<<(N_NODES * 32 + 255) / 256, 256>>>(b1);
    gemm2K  <<<(N_NODES + NT2 - 1) / NT2, 320>>>(W2, as2, ad2);
    gather2K<<<(N_NODES * 32 + 255) / 256, 256>>>(b2, out);
}

// round 15
// speedup vs baseline: 1.0694x; 1.0694x over previous
#include <cuda_runtime.h>
#include <cuda_fp16.h>
#include <math.h>

#define N_NODES 50000
#define FEAT    120
#define TOPO    8
#define KIN     128   // FEAT + TOPO
#define H1D1    64    // 8 heads * 8 dim
#define NH      8
#define D1      8
#define C       40
#define NEG     0.2f
#define EMAX_TOT (800000 + N_NODES)
#define NB_SCAN ((N_NODES + 1023) / 1024)

// ---- scratch (device globals; no allocation allowed) ----
__device__ __align__(16) __half g_h1h[N_NODES * H1D1];   // layer-1 features, fp16
__device__ float g_als1[N_NODES * NH];
__device__ float g_ald1[N_NODES * NH];
__device__ __align__(16) __half g_h2h[N_NODES * H1D1];   // layer-1 output (post ELU), fp16
__device__ __align__(16) __half g_g2h[N_NODES * C];      // layer-2 features, fp16
__device__ float g_als2[N_NODES];
__device__ float g_ald2[N_NODES];
// CSR scratch
__device__ struct CsrTmp {
    int cnt[N_NODES];
    unsigned long long state[NB_SCAN];
} g_tmp;
__device__ int g_off[N_NODES + 1];
__device__ unsigned short g_slot[EMAX_TOT];
__device__ unsigned short g_csr_src[EMAX_TOT];

__device__ __forceinline__ float lrelu(float x) { return x > 0.0f ? x : NEG * x; }

// ---- fork/join stream + events ----
static cudaStream_t s_side;
static cudaEvent_t  s_evFork, s_evJoin;
namespace {
struct StreamInit {
    StreamInit() {
        cudaStreamCreateWithFlags(&s_side, cudaStreamNonBlocking);
        cudaEventCreateWithFlags(&s_evFork, cudaEventDisableTiming);
        cudaEventCreateWithFlags(&s_evJoin, cudaEventDisableTiming);
    }
} s_streamInit;
}

// ======================= CSR build =======================
__global__ void histK(const int* __restrict__ ei, int E, int Etot) {
    if (blockIdx.x == 0 && threadIdx.x < NB_SCAN) g_tmp.state[threadIdx.x] = 0ULL;
    int base = blockIdx.x * (blockDim.x * 4) + threadIdx.x;
#pragma unroll
    for (int r = 0; r < 4; ++r) {
        int e = base + r * blockDim.x;
        if (e < Etot) {
            int d = (e < E) ? ei[E + e] : (e - E);
            int old = atomicAdd(&g_tmp.cnt[d], 1);
            g_slot[e] = (unsigned short)old;
        }
    }
}

__global__ __launch_bounds__(1024) void scanK() {
    int b = blockIdx.x, t = threadIdx.x;
    int i = b * 1024 + t;
    int lane = t & 31, wid = t >> 5;
    int v = (i < N_NODES) ? g_tmp.cnt[i] : 0;
    if (i < N_NODES) g_tmp.cnt[i] = 0;
    int x = v;
#pragma unroll
    for (int off = 1; off < 32; off <<= 1) {
        int y = __shfl_up_sync(0xffffffffu, x, off);
        if (lane >= off) x += y;
    }
    __shared__ int wsum[32];
    if (lane == 31) wsum[wid] = x;
    __syncthreads();
    if (wid == 0) {
        int w = wsum[lane];
#pragma unroll
        for (int off = 1; off < 32; off <<= 1) {
            int y = __shfl_up_sync(0xffffffffu, w, off);
            if (lane >= off) w += y;
        }
        wsum[lane] = w;
    }
    __syncthreads();
    int blockIncl = x + (wid ? wsum[wid - 1] : 0);
    int total = wsum[31];

    __shared__ int s_prefix;
    if (t == 0) {
        if (b == 0) {
            atomicExch(&g_tmp.state[0], (2ULL << 32) | (unsigned)total);
            s_prefix = 0;
        } else {
            atomicExch(&g_tmp.state[b], (1ULL << 32) | (unsigned)total);
            int prefix = 0;
            for (int j = b - 1; j >= 0; --j) {
                unsigned long long st;
                do { st = atomicAdd(&g_tmp.state[j], 0ULL); } while ((st >> 32) == 0ULL);
                prefix += (int)(unsigned)st;
                if ((st >> 32) == 2ULL) break;
            }
            atomicExch(&g_tmp.state[b], (2ULL << 32) | (unsigned)(prefix + total));
            s_prefix = prefix;
        }
    }
    __syncthreads();
    if (i < N_NODES) g_off[i] = s_prefix + blockIncl - v;
    if (i == N_NODES - 1) g_off[N_NODES] = s_prefix + blockIncl;
}

__global__ void scatterK(const int* __restrict__ ei, int E, int Etot) {
    int base = blockIdx.x * (blockDim.x * 4) + threadIdx.x;
#pragma unroll
    for (int r = 0; r < 4; ++r) {
        int e = base + r * blockDim.x;
        if (e < Etot) {
            int s, d;
            if (e < E) { s = ei[e]; d = ei[E + e]; } else { s = d = e - E; }
            int pos = g_off[d] + (int)g_slot[e];
            g_csr_src[pos] = (unsigned short)s;
        }
    }
}

// ======================= Layer 1 GEMM (tiled, fp16 output) =======================
#define NT1 64
__global__ __launch_bounds__(256) void gemm1K(
        const float* __restrict__ x, const float* __restrict__ topo,
        const float* __restrict__ W1, const float* __restrict__ as1,
        const float* __restrict__ ad1) {
    __shared__ float xs[NT1][132];
    __shared__ float wt[64][132];
    __shared__ float hs[NT1][65];
    __shared__ float sas[64], sad[64];
    int t = threadIdx.x;
    int nbase = blockIdx.x * NT1;

    if (t < 64) { sas[t] = as1[t]; sad[t] = ad1[t]; }
    for (int i = t; i < 128 * 64; i += 256) {
        int k = i >> 6, c = i & 63;
        wt[c][k] = W1[i];
    }
    for (int i = t; i < NT1 * 128; i += 256) {
        int nl = i >> 7, k = i & 127;
        int n = nbase + nl;
        float v = 0.f;
        if (n < N_NODES) v = (k < FEAT) ? x[n * FEAT + k] : topo[n * TOPO + (k - FEAT)];
        xs[nl][k] = v;
    }
    __syncthreads();

    int cg = t & 15;
    int ng = t >> 4;
    float acc[4][4] = {};
#pragma unroll 4
    for (int k = 0; k < 128; k += 4) {
        float4 w0 = *(const float4*)&wt[cg][k];
        float4 w1v = *(const float4*)&wt[cg + 16][k];
        float4 w2v = *(const float4*)&wt[cg + 32][k];
        float4 w3v = *(const float4*)&wt[cg + 48][k];
#pragma unroll
        for (int u = 0; u < 4; ++u) {
            float4 xv = *(const float4*)&xs[ng * 4 + u][k];
            acc[u][0] += xv.x*w0.x + xv.y*w0.y + xv.z*w0.z + xv.w*w0.w;
            acc[u][1] += xv.x*w1v.x + xv.y*w1v.y + xv.z*w1v.z + xv.w*w1v.w;
            acc[u][2] += xv.x*w2v.x + xv.y*w2v.y + xv.z*w2v.z + xv.w*w2v.w;
            acc[u][3] += xv.x*w3v.x + xv.y*w3v.y + xv.z*w3v.z + xv.w*w3v.w;
        }
    }
#pragma unroll
    for (int u = 0; u < 4; ++u) {
        int nl = ng * 4 + u;
#pragma unroll
        for (int j = 0; j < 4; ++j)
            hs[nl][cg + j * 16] = acc[u][j];
    }
    __syncthreads();
#pragma unroll
    for (int rep = 0; rep < 2; ++rep) {
        int idx = t + rep * 256;
        int nl = idx >> 3, h = idx & 7;
        int n = nbase + nl;
        if (n < N_NODES) {
            float ts = 0.f, td = 0.f;
#pragma unroll
            for (int q = 0; q < 8; ++q) {
                float hv = hs[nl][h * 8 + q];
                ts = fmaf(hv, sas[h * 8 + q], ts);
                td = fmaf(hv, sad[h * 8 + q], td);
            }
            g_als1[n * NH + h] = ts;
            g_ald1[n * NH + h] = td;
        }
    }
    for (int i = t; i < NT1 * 8; i += 256) {
        int nl = i >> 3, q = i & 7;
        int n = nbase + nl;
        if (n < N_NODES) {
            __half2 hv[4];
#pragma unroll
            for (int j = 0; j < 4; ++j)
                hv[j] = __floats2half2_rn(hs[nl][q * 8 + j * 2], hs[nl][q * 8 + j * 2 + 1]);
            *(uint4*)(g_h1h + (size_t)n * H1D1 + q * 8) = *(uint4*)hv;
        }
    }
}

// ========== Layer 1 gather: group-owns-edge, 8-edge batched, fp16 h2 out ==========
__global__ void gather1K(const float* __restrict__ b1) {
    int w = (blockIdx.x * blockDim.x + threadIdx.x) >> 5;
    if (w >= N_NODES) return;
    int lane = threadIdx.x & 31;
    int g = lane >> 3, l = lane & 7;
    int d = w;
    int beg = g_off[d], end = g_off[d + 1];
    float ald = g_ald1[d * NH + l];
    float acc[8] = {};
    float s = 0.f;
    int last = end - 1;

    for (int i = beg; i < end; i += 8) {
        int e0 = i + g, e1 = i + g + 4;
        bool v0 = e0 < end, v1 = e1 < end;
        int c0 = v0 ? e0 : last, c1 = v1 ? e1 : last;
        int s0 = (int)g_csr_src[c0];
        int s1 = (int)g_csr_src[c1];
        float a0 = g_als1[s0 * NH + l];
        float a1 = g_als1[s1 * NH + l];
        uint4 r0 = *(const uint4*)(g_h1h + (size_t)s0 * H1D1 + l * 8);
        uint4 r1 = *(const uint4*)(g_h1h + (size_t)s1 * H1D1 + l * 8);
        float p0 = v0 ? __expf(lrelu(a0 + ald)) : 0.f;
        float p1 = v1 ? __expf(lrelu(a1 + ald)) : 0.f;
        s += p0 + p1;
        float2 f;
        f = __half22float2(*(__half2*)&r0.x); acc[0] = fmaf(p0, f.x, acc[0]); acc[1] = fmaf(p0, f.y, acc[1]);
        f = __half22float2(*(__half2*)&r0.y); acc[2] = fmaf(p0, f.x, acc[2]); acc[3] = fmaf(p0, f.y, acc[3]);
        f = __half22float2(*(__half2*)&r0.z); acc[4] = fmaf(p0, f.x, acc[4]); acc[5] = fmaf(p0, f.y, acc[5]);
        f = __half22float2(*(__half2*)&r0.w); acc[6] = fmaf(p0, f.x, acc[6]); acc[7] = fmaf(p0, f.y, acc[7]);
        f = __half22float2(*(__half2*)&r1.x); acc[0] = fmaf(p1, f.x, acc[0]); acc[1] = fmaf(p1, f.y, acc[1]);
        f = __half22float2(*(__half2*)&r1.y); acc[2] = fmaf(p1, f.x, acc[2]); acc[3] = fmaf(p1, f.y, acc[3]);
        f = __half22float2(*(__half2*)&r1.z); acc[4] = fmaf(p1, f.x, acc[4]); acc[5] = fmaf(p1, f.y, acc[5]);
        f = __half22float2(*(__half2*)&r1.w); acc[6] = fmaf(p1, f.x, acc[6]); acc[7] = fmaf(p1, f.y, acc[7]);
    }
#pragma unroll
    for (int j = 0; j < 8; ++j) {
        acc[j] += __shfl_xor_sync(0xffffffffu, acc[j], 8);
        acc[j] += __shfl_xor_sync(0xffffffffu, acc[j], 16);
    }
    s += __shfl_xor_sync(0xffffffffu, s, 8);
    s += __shfl_xor_sync(0xffffffffu, s, 16);
    float inv = 1.f / s;
    if (g == 0) {
        float4 bv = *(const float4*)(b1 + l * 8);
        float4 v;
        v.x = acc[0] * inv + bv.x; v.y = acc[1] * inv + bv.y;
        v.z = acc[2] * inv + bv.z; v.w = acc[3] * inv + bv.w;
        v.x = v.x > 0.f ? v.x : expm1f(v.x); v.y = v.y > 0.f ? v.y : expm1f(v.y);
        v.z = v.z > 0.f ? v.z : expm1f(v.z); v.w = v.w > 0.f ? v.w : expm1f(v.w);
        union { __half2 h[2]; uint2 u2; } pk;
        pk.h[0] = __floats2half2_rn(v.x, v.y);
        pk.h[1] = __floats2half2_rn(v.z, v.w);
        *(uint2*)(g_h2h + (size_t)d * H1D1 + l * 8) = pk.u2;
    } else if (g == 1) {
        float4 bv = *(const float4*)(b1 + l * 8 + 4);
        float4 v;
        v.x = acc[4] * inv + bv.x; v.y = acc[5] * inv + bv.y;
        v.z = acc[6] * inv + bv.z; v.w = acc[7] * inv + bv.w;
        v.x = v.x > 0.f ? v.x : expm1f(v.x); v.y = v.y > 0.f ? v.y : expm1f(v.y);
        v.z = v.z > 0.f ? v.z : expm1f(v.z); v.w = v.w > 0.f ? v.w : expm1f(v.w);
        union { __half2 h[2]; uint2 u2; } pk;
        pk.h[0] = __floats2half2_rn(v.x, v.y);
        pk.h[1] = __floats2half2_rn(v.z, v.w);
        *(uint2*)(g_h2h + (size_t)d * H1D1 + l * 8 + 4) = pk.u2;
    }
}

// ======================= Layer 2 GEMM (NT2=128, fp16 in/out) =======================
#define NT2 128
__global__ __launch_bounds__(320) void gemm2K(
        const float* __restrict__ W2, const float* __restrict__ as2,
        const float* __restrict__ ad2) {
    __shared__ float xs2[NT2][68];
    __shared__ float ws2[64][44];
    __shared__ float sas[40], sad[40];
    int t = threadIdx.x;
    int nbase = blockIdx.x * NT2;

    if (t < 40) { sas[t] = as2[t]; sad[t] = ad2[t]; }
    for (int i = t; i < 64 * C; i += 320) {
        int k = i / C, c = i - k * C;
        ws2[k][c] = W2[i];
    }
    // load h2 (fp16) -> fp32 smem: NT2 rows x 32 half2 each
    for (int i = t; i < NT2 * 32; i += 320) {
        int nl = i >> 5, k2 = i & 31;
        int n = nbase + nl;
        float2 f = make_float2(0.f, 0.f);
        if (n < N_NODES)
            f = __half22float2(*(const __half2*)(g_h2h + (size_t)n * H1D1 + k2 * 2));
        xs2[nl][k2 * 2]     = f.x;
        xs2[nl][k2 * 2 + 1] = f.y;
    }
    __syncthreads();

    int cg = t % 10;
    int ng = t / 10;
    float acc[4][4] = {};
#pragma unroll 4
    for (int k = 0; k < 64; k += 4) {
        float4 w0 = *(const float4*)&ws2[k + 0][cg * 4];
        float4 w1v = *(const float4*)&ws2[k + 1][cg * 4];
        float4 w2v = *(const float4*)&ws2[k + 2][cg * 4];
        float4 w3v = *(const float4*)&ws2[k + 3][cg * 4];
#pragma unroll
        for (int u = 0; u < 4; ++u) {
            float4 xv = *(const float4*)&xs2[ng * 4 + u][k];
            acc[u][0] += xv.x*w0.x + xv.y*w1v.x + xv.z*w2v.x + xv.w*w3v.x;
            acc[u][1] += xv.x*w0.y + xv.y*w1v.y + xv.z*w2v.y + xv.w*w3v.y;
            acc[u][2] += xv.x*w0.z + xv.y*w1v.z + xv.z*w2v.z + xv.w*w3v.z;
            acc[u][3] += xv.x*w0.w + xv.y*w1v.w + xv.z*w2v.w + xv.w*w3v.w;
        }
    }
    __syncthreads();
#pragma unroll
    for (int u = 0; u < 4; ++u) {
        int nl = ng * 4 + u;
        int n = nbase + nl;
#pragma unroll
        for (int j = 0; j < 4; ++j) xs2[nl][cg * 4 + j] = acc[u][j];
        if (n < N_NODES) {
            union { __half2 h[2]; uint2 u2; } pk;
            pk.h[0] = __floats2half2_rn(acc[u][0], acc[u][1]);
            pk.h[1] = __floats2half2_rn(acc[u][2], acc[u][3]);
            *(uint2*)(g_g2h + (size_t)n * C + cg * 4) = pk.u2;
        }
    }
    __syncthreads();
    if (t < NT2) {
        int n = nbase + t;
        if (n < N_NODES) {
            float ts = 0.f, td = 0.f;
#pragma unroll 8
            for (int c = 0; c < C; ++c) {
                float gv = xs2[t][c];
                ts = fmaf(gv, sas[c], ts);
                td = fmaf(gv, sad[c], td);
            }
            g_als2[n] = ts;
            g_ald2[n] = td;
        }
    }
}

// ========== Layer 2 gather: group-owns-edge, fp16 g2 (lanes 0-4 carry 8 cols each) ==========
__global__ void gather2K(const float* __restrict__ b2, float* __restrict__ out) {
    int w = (blockIdx.x * blockDim.x + threadIdx.x) >> 5;
    if (w >= N_NODES) return;
    int lane = threadIdx.x & 31;
    int g = lane >> 3, l = lane & 7;
    int d = w;
    int beg = g_off[d], end = g_off[d + 1];
    float ald = g_ald2[d];
    float acc[8] = {};
    float s = 0.f;
    int last = end - 1;
    bool feat = (l < 5);
    int fcol = feat ? l * 8 : 0;

    for (int i = beg; i < end; i += 8) {
        int e0 = i + g, e1 = i + g + 4;
        bool v0 = e0 < end, v1 = e1 < end;
        int c0 = v0 ? e0 : last, c1 = v1 ? e1 : last;
        int s0 = (int)g_csr_src[c0];
        int s1 = (int)g_csr_src[c1];
        float a0 = g_als2[s0];
        float a1 = g_als2[s1];
        uint4 r0 = make_uint4(0, 0, 0, 0), r1 = make_uint4(0, 0, 0, 0);
        if (feat) {
            r0 = *(const uint4*)(g_g2h + (size_t)s0 * C + fcol);
            r1 = *(const uint4*)(g_g2h + (size_t)s1 * C + fcol);
        }
        float p0 = v0 ? __expf(lrelu(a0 + ald)) : 0.f;
        float p1 = v1 ? __expf(lrelu(a1 + ald)) : 0.f;
        s += p0 + p1;
        float2 f;
        f = __half22float2(*(__half2*)&r0.x); acc[0] = fmaf(p0, f.x, acc[0]); acc[1] = fmaf(p0, f.y, acc[1]);
        f = __half22float2(*(__half2*)&r0.y); acc[2] = fmaf(p0, f.x, acc[2]); acc[3] = fmaf(p0, f.y, acc[3]);
        f = __half22float2(*(__half2*)&r0.z); acc[4] = fmaf(p0, f.x, acc[4]); acc[5] = fmaf(p0, f.y, acc[5]);
        f = __half22float2(*(__half2*)&r0.w); acc[6] = fmaf(p0, f.x, acc[6]); acc[7] = fmaf(p0, f.y, acc[7]);
        f = __half22float2(*(__half2*)&r1.x); acc[0] = fmaf(p1, f.x, acc[0]); acc[1] = fmaf(p1, f.y, acc[1]);
        f = __half22float2(*(__half2*)&r1.y); acc[2] = fmaf(p1, f.x, acc[2]); acc[3] = fmaf(p1, f.y, acc[3]);
        f = __half22float2(*(__half2*)&r1.z); acc[4] = fmaf(p1, f.x, acc[4]); acc[5] = fmaf(p1, f.y, acc[5]);
        f = __half22float2(*(__half2*)&r1.w); acc[6] = fmaf(p1, f.x, acc[6]); acc[7] = fmaf(p1, f.y, acc[7]);
    }
#pragma unroll
    for (int j = 0; j < 8; ++j) {
        acc[j] += __shfl_xor_sync(0xffffffffu, acc[j], 8);
        acc[j] += __shfl_xor_sync(0xffffffffu, acc[j], 16);
    }
    s += __shfl_xor_sync(0xffffffffu, s, 8);
    s += __shfl_xor_sync(0xffffffffu, s, 16);
    float inv = 1.f / s;

    float v[8];
    float m = -INFINITY;
    if (feat) {
#pragma unroll
        for (int j = 0; j < 8; ++j) {
            v[j] = acc[j] * inv + b2[fcol + j];
            m = fmaxf(m, v[j]);
        }
    }
#pragma unroll
    for (int off = 1; off < 8; off <<= 1)
        m = fmaxf(m, __shfl_xor_sync(0xffffffffu, m, off));
    float es = 0.f;
    if (feat) {
#pragma unroll
        for (int j = 0; j < 8; ++j) es += expf(v[j] - m);
    }
#pragma unroll
    for (int off = 1; off < 8; off <<= 1)
        es += __shfl_xor_sync(0xffffffffu, es, off);
    float lse = logf(es) + m;
    if (g == 0 && feat) {
        float4 o0 = make_float4(v[0] - lse, v[1] - lse, v[2] - lse, v[3] - lse);
        float4 o1 = make_float4(v[4] - lse, v[5] - lse, v[6] - lse, v[7] - lse);
        *(float4*)(out + (size_t)d * C + fcol)     = o0;
        *(float4*)(out + (size_t)d * C + fcol + 4) = o1;
    }
}

extern "C" void kernel_launch(void* const* d_in, const int* in_sizes, int n_in,
                              void* d_out, int out_size) {
    const float* x    = (const float*)d_in[0];
    const float* topo = (const float*)d_in[1];
    const int*   ei   = (const int*)  d_in[2];
    const float* W1   = (const float*)d_in[3];
    const float* as1  = (const float*)d_in[4];
    const float* ad1  = (const float*)d_in[5];
    const float* b1   = (const float*)d_in[6];
    const float* W2   = (const float*)d_in[7];
    const float* as2  = (const float*)d_in[8];
    const float* ad2  = (const float*)d_in[9];
    const float* b2   = (const float*)d_in[10];
    float* out = (float*)d_out;

    int E    = in_sizes[2] / 2;
    int Etot = E + N_NODES;

    // fork: gemm1 runs concurrently with the CSR build
    cudaEventRecord(s_evFork, 0);
    cudaStreamWaitEvent(s_side, s_evFork, 0);
    gemm1K<<<(N_NODES + NT1 - 1) / NT1, 256, 0, s_side>>>(x, topo, W1, as1, ad1);
    cudaEventRecord(s_evJoin, s_side);

    // CSR build (no memset: cnt self-clears in scanK, state zeroed in histK)
    histK   <<<(Etot + 1023) / 1024, 256>>>(ei, E, Etot);
    scanK   <<<NB_SCAN, 1024>>>();
    scatterK<<<(Etot + 1023) / 1024, 256>>>(ei, E, Etot);

    // join, then the dependent chain
    cudaStreamWaitEvent(0, s_evJoin, 0);
    gather1K<<<(N_NODES * 32 + 255) / 256, 256>>>(b1);
    gemm2K  <<<(N_NODES + NT2 - 1) / NT2, 320>>>(W2, as2, ad2);
    gather2K<<<(N_NODES * 32 + 255) / 256, 256>>>(b2, out);
}

// round 16
// speedup vs baseline: 1.0900x; 1.0193x over previous
#include <cuda_runtime.h>
#include <cuda_fp16.h>
#include <math.h>

#define N_NODES 50000
#define FEAT    120
#define TOPO    8
#define KIN     128   // FEAT + TOPO
#define H1D1    64    // 8 heads * 8 dim
#define NH      8
#define D1      8
#define C       40
#define NEG     0.2f
#define EMAX_TOT (800000 + N_NODES)
#define NB_SCAN ((N_NODES + 1023) / 1024)

// ---- scratch (device globals; no allocation allowed) ----
__device__ __align__(16) __half g_h1h[N_NODES * H1D1];   // layer-1 features, fp16
__device__ float g_als1[N_NODES * NH];
__device__ float g_ald1[N_NODES * NH];
__device__ __align__(16) __half g_h2h[N_NODES * H1D1];   // layer-1 output (post ELU), fp16
__device__ __align__(16) __half g_g2h[N_NODES * C];      // layer-2 features, fp16
__device__ float g_als2[N_NODES];
__device__ float g_ald2[N_NODES];
// CSR scratch
__device__ struct CsrTmp {
    int cnt[N_NODES];
    unsigned long long state[NB_SCAN];
} g_tmp;
__device__ int g_off[N_NODES + 1];
__device__ unsigned short g_slot[EMAX_TOT];
__device__ unsigned short g_csr_src[EMAX_TOT];

__device__ __forceinline__ float lrelu(float x) { return x > 0.0f ? x : NEG * x; }

// ---- fork/join stream + events ----
static cudaStream_t s_side;
static cudaEvent_t  s_evFork, s_evJoin;
namespace {
struct StreamInit {
    StreamInit() {
        cudaStreamCreateWithFlags(&s_side, cudaStreamNonBlocking);
        cudaEventCreateWithFlags(&s_evFork, cudaEventDisableTiming);
        cudaEventCreateWithFlags(&s_evJoin, cudaEventDisableTiming);
    }
} s_streamInit;
}

// ======================= CSR build =======================
__global__ void histK(const int* __restrict__ ei, int E, int Etot) {
    if (blockIdx.x == 0 && threadIdx.x < NB_SCAN) g_tmp.state[threadIdx.x] = 0ULL;
    int base = blockIdx.x * (blockDim.x * 4) + threadIdx.x;
#pragma unroll
    for (int r = 0; r < 4; ++r) {
        int e = base + r * blockDim.x;
        if (e < Etot) {
            int d = (e < E) ? ei[E + e] : (e - E);
            int old = atomicAdd(&g_tmp.cnt[d], 1);
            g_slot[e] = (unsigned short)old;
        }
    }
}

// PDL secondary of histK: sync before reading cnt/state.
__global__ __launch_bounds__(1024) void scanK() {
    cudaGridDependencySynchronize();
    int b = blockIdx.x, t = threadIdx.x;
    int i = b * 1024 + t;
    int lane = t & 31, wid = t >> 5;
    int v = (i < N_NODES) ? g_tmp.cnt[i] : 0;
    if (i < N_NODES) g_tmp.cnt[i] = 0;
    int x = v;
#pragma unroll
    for (int off = 1; off < 32; off <<= 1) {
        int y = __shfl_up_sync(0xffffffffu, x, off);
        if (lane >= off) x += y;
    }
    __shared__ int wsum[32];
    if (lane == 31) wsum[wid] = x;
    __syncthreads();
    if (wid == 0) {
        int w = wsum[lane];
#pragma unroll
        for (int off = 1; off < 32; off <<= 1) {
            int y = __shfl_up_sync(0xffffffffu, w, off);
            if (lane >= off) w += y;
        }
        wsum[lane] = w;
    }
    __syncthreads();
    int blockIncl = x + (wid ? wsum[wid - 1] : 0);
    int total = wsum[31];

    __shared__ int s_prefix;
    if (t == 0) {
        if (b == 0) {
            atomicExch(&g_tmp.state[0], (2ULL << 32) | (unsigned)total);
            s_prefix = 0;
        } else {
            atomicExch(&g_tmp.state[b], (1ULL << 32) | (unsigned)total);
            int prefix = 0;
            for (int j = b - 1; j >= 0; --j) {
                unsigned long long st;
                do { st = atomicAdd(&g_tmp.state[j], 0ULL); } while ((st >> 32) == 0ULL);
                prefix += (int)(unsigned)st;
                if ((st >> 32) == 2ULL) break;
            }
            atomicExch(&g_tmp.state[b], (2ULL << 32) | (unsigned)(prefix + total));
            s_prefix = prefix;
        }
    }
    __syncthreads();
    if (i < N_NODES) g_off[i] = s_prefix + blockIncl - v;
    if (i == N_NODES - 1) g_off[N_NODES] = s_prefix + blockIncl;
}

// PDL secondary of scanK: preload edge_index (input) pre-sync, then off/slot post-sync.
__global__ void scatterK(const int* __restrict__ ei, int E, int Etot) {
    int base = blockIdx.x * (blockDim.x * 4) + threadIdx.x;
    int rs[4], rd[4];
#pragma unroll
    for (int r = 0; r < 4; ++r) {
        int e = base + r * blockDim.x;
        rd[r] = -1;
        if (e < Etot) {
            if (e < E) { rs[r] = ei[e]; rd[r] = ei[E + e]; }
            else       { rs[r] = rd[r] = e - E; }
        }
    }
    cudaGridDependencySynchronize();
#pragma unroll
    for (int r = 0; r < 4; ++r) {
        if (rd[r] >= 0) {
            int e = base + r * blockDim.x;
            int pos = g_off[rd[r]] + (int)g_slot[e];
            g_csr_src[pos] = (unsigned short)rs[r];
        }
    }
}

// ======================= Layer 1 GEMM (tiled, fp16 output) =======================
#define NT1 64
__global__ __launch_bounds__(256) void gemm1K(
        const float* __restrict__ x, const float* __restrict__ topo,
        const float* __restrict__ W1, const float* __restrict__ as1,
        const float* __restrict__ ad1) {
    __shared__ float xs[NT1][132];
    __shared__ float wt[64][132];
    __shared__ float hs[NT1][65];
    __shared__ float sas[64], sad[64];
    int t = threadIdx.x;
    int nbase = blockIdx.x * NT1;

    if (t < 64) { sas[t] = as1[t]; sad[t] = ad1[t]; }
    for (int i = t; i < 128 * 64; i += 256) {
        int k = i >> 6, c = i & 63;
        wt[c][k] = W1[i];
    }
    for (int i = t; i < NT1 * 128; i += 256) {
        int nl = i >> 7, k = i & 127;
        int n = nbase + nl;
        float v = 0.f;
        if (n < N_NODES) v = (k < FEAT) ? x[n * FEAT + k] : topo[n * TOPO + (k - FEAT)];
        xs[nl][k] = v;
    }
    __syncthreads();

    int cg = t & 15;
    int ng = t >> 4;
    float acc[4][4] = {};
#pragma unroll 4
    for (int k = 0; k < 128; k += 4) {
        float4 w0 = *(const float4*)&wt[cg][k];
        float4 w1v = *(const float4*)&wt[cg + 16][k];
        float4 w2v = *(const float4*)&wt[cg + 32][k];
        float4 w3v = *(const float4*)&wt[cg + 48][k];
#pragma unroll
        for (int u = 0; u < 4; ++u) {
            float4 xv = *(const float4*)&xs[ng * 4 + u][k];
            acc[u][0] += xv.x*w0.x + xv.y*w0.y + xv.z*w0.z + xv.w*w0.w;
            acc[u][1] += xv.x*w1v.x + xv.y*w1v.y + xv.z*w1v.z + xv.w*w1v.w;
            acc[u][2] += xv.x*w2v.x + xv.y*w2v.y + xv.z*w2v.z + xv.w*w2v.w;
            acc[u][3] += xv.x*w3v.x + xv.y*w3v.y + xv.z*w3v.z + xv.w*w3v.w;
        }
    }
#pragma unroll
    for (int u = 0; u < 4; ++u) {
        int nl = ng * 4 + u;
#pragma unroll
        for (int j = 0; j < 4; ++j)
            hs[nl][cg + j * 16] = acc[u][j];
    }
    __syncthreads();
#pragma unroll
    for (int rep = 0; rep < 2; ++rep) {
        int idx = t + rep * 256;
        int nl = idx >> 3, h = idx & 7;
        int n = nbase + nl;
        if (n < N_NODES) {
            float ts = 0.f, td = 0.f;
#pragma unroll
            for (int q = 0; q < 8; ++q) {
                float hv = hs[nl][h * 8 + q];
                ts = fmaf(hv, sas[h * 8 + q], ts);
                td = fmaf(hv, sad[h * 8 + q], td);
            }
            g_als1[n * NH + h] = ts;
            g_ald1[n * NH + h] = td;
        }
    }
    for (int i = t; i < NT1 * 8; i += 256) {
        int nl = i >> 3, q = i & 7;
        int n = nbase + nl;
        if (n < N_NODES) {
            __half2 hv[4];
#pragma unroll
            for (int j = 0; j < 4; ++j)
                hv[j] = __floats2half2_rn(hs[nl][q * 8 + j * 2], hs[nl][q * 8 + j * 2 + 1]);
            *(uint4*)(g_h1h + (size_t)n * H1D1 + q * 8) = *(uint4*)hv;
        }
    }
}

// ========== Layer 1 gather: group-owns-edge, 8-edge batched, fp16 h2 out ==========
__global__ void gather1K(const float* __restrict__ b1) {
    int w = (blockIdx.x * blockDim.x + threadIdx.x) >> 5;
    if (w >= N_NODES) return;
    int lane = threadIdx.x & 31;
    int g = lane >> 3, l = lane & 7;
    int d = w;
    int beg = g_off[d], end = g_off[d + 1];
    float ald = g_ald1[d * NH + l];
    float acc[8] = {};
    float s = 0.f;
    int last = end - 1;

    for (int i = beg; i < end; i += 8) {
        int e0 = i + g, e1 = i + g + 4;
        bool v0 = e0 < end, v1 = e1 < end;
        int c0 = v0 ? e0 : last, c1 = v1 ? e1 : last;
        int s0 = (int)g_csr_src[c0];
        int s1 = (int)g_csr_src[c1];
        float a0 = g_als1[s0 * NH + l];
        float a1 = g_als1[s1 * NH + l];
        uint4 r0 = *(const uint4*)(g_h1h + (size_t)s0 * H1D1 + l * 8);
        uint4 r1 = *(const uint4*)(g_h1h + (size_t)s1 * H1D1 + l * 8);
        float p0 = v0 ? __expf(lrelu(a0 + ald)) : 0.f;
        float p1 = v1 ? __expf(lrelu(a1 + ald)) : 0.f;
        s += p0 + p1;
        float2 f;
        f = __half22float2(*(__half2*)&r0.x); acc[0] = fmaf(p0, f.x, acc[0]); acc[1] = fmaf(p0, f.y, acc[1]);
        f = __half22float2(*(__half2*)&r0.y); acc[2] = fmaf(p0, f.x, acc[2]); acc[3] = fmaf(p0, f.y, acc[3]);
        f = __half22float2(*(__half2*)&r0.z); acc[4] = fmaf(p0, f.x, acc[4]); acc[5] = fmaf(p0, f.y, acc[5]);
        f = __half22float2(*(__half2*)&r0.w); acc[6] = fmaf(p0, f.x, acc[6]); acc[7] = fmaf(p0, f.y, acc[7]);
        f = __half22float2(*(__half2*)&r1.x); acc[0] = fmaf(p1, f.x, acc[0]); acc[1] = fmaf(p1, f.y, acc[1]);
        f = __half22float2(*(__half2*)&r1.y); acc[2] = fmaf(p1, f.x, acc[2]); acc[3] = fmaf(p1, f.y, acc[3]);
        f = __half22float2(*(__half2*)&r1.z); acc[4] = fmaf(p1, f.x, acc[4]); acc[5] = fmaf(p1, f.y, acc[5]);
        f = __half22float2(*(__half2*)&r1.w); acc[6] = fmaf(p1, f.x, acc[6]); acc[7] = fmaf(p1, f.y, acc[7]);
    }
#pragma unroll
    for (int j = 0; j < 8; ++j) {
        acc[j] += __shfl_xor_sync(0xffffffffu, acc[j], 8);
        acc[j] += __shfl_xor_sync(0xffffffffu, acc[j], 16);
    }
    s += __shfl_xor_sync(0xffffffffu, s, 8);
    s += __shfl_xor_sync(0xffffffffu, s, 16);
    float inv = 1.f / s;
    if (g == 0) {
        float4 bv = *(const float4*)(b1 + l * 8);
        float4 v;
        v.x = acc[0] * inv + bv.x; v.y = acc[1] * inv + bv.y;
        v.z = acc[2] * inv + bv.z; v.w = acc[3] * inv + bv.w;
        v.x = v.x > 0.f ? v.x : expm1f(v.x); v.y = v.y > 0.f ? v.y : expm1f(v.y);
        v.z = v.z > 0.f ? v.z : expm1f(v.z); v.w = v.w > 0.f ? v.w : expm1f(v.w);
        union { __half2 h[2]; uint2 u2; } pk;
        pk.h[0] = __floats2half2_rn(v.x, v.y);
        pk.h[1] = __floats2half2_rn(v.z, v.w);
        *(uint2*)(g_h2h + (size_t)d * H1D1 + l * 8) = pk.u2;
    } else if (g == 1) {
        float4 bv = *(const float4*)(b1 + l * 8 + 4);
        float4 v;
        v.x = acc[4] * inv + bv.x; v.y = acc[5] * inv + bv.y;
        v.z = acc[6] * inv + bv.z; v.w = acc[7] * inv + bv.w;
        v.x = v.x > 0.f ? v.x : expm1f(v.x); v.y = v.y > 0.f ? v.y : expm1f(v.y);
        v.z = v.z > 0.f ? v.z : expm1f(v.z); v.w = v.w > 0.f ? v.w : expm1f(v.w);
        union { __half2 h[2]; uint2 u2; } pk;
        pk.h[0] = __floats2half2_rn(v.x, v.y);
        pk.h[1] = __floats2half2_rn(v.z, v.w);
        *(uint2*)(g_h2h + (size_t)d * H1D1 + l * 8 + 4) = pk.u2;
    }
}

// ===== Layer 2 GEMM (NT2=128, fp16 in/out). PDL secondary of gather1K:
// W2/attn smem fill happens BEFORE the dependency sync (overlaps gather1 tail). =====
#define NT2 128
__global__ __launch_bounds__(320) void gemm2K(
        const float* __restrict__ W2, const float* __restrict__ as2,
        const float* __restrict__ ad2) {
    __shared__ float xs2[NT2][68];
    __shared__ float ws2[64][44];
    __shared__ float sas[40], sad[40];
    int t = threadIdx.x;
    int nbase = blockIdx.x * NT2;

    if (t < 40) { sas[t] = as2[t]; sad[t] = ad2[t]; }
    for (int i = t; i < 64 * C; i += 320) {
        int k = i / C, c = i - k * C;
        ws2[k][c] = W2[i];
    }
    cudaGridDependencySynchronize();      // wait for gather1K's h2 before reading it
    // load h2 (fp16) -> fp32 smem: NT2 rows x 32 half2 each
    for (int i = t; i < NT2 * 32; i += 320) {
        int nl = i >> 5, k2 = i & 31;
        int n = nbase + nl;
        float2 f = make_float2(0.f, 0.f);
        if (n < N_NODES)
            f = __half22float2(*(const __half2*)(g_h2h + (size_t)n * H1D1 + k2 * 2));
        xs2[nl][k2 * 2]     = f.x;
        xs2[nl][k2 * 2 + 1] = f.y;
    }
    __syncthreads();

    int cg = t % 10;
    int ng = t / 10;
    float acc[4][4] = {};
#pragma unroll 4
    for (int k = 0; k < 64; k += 4) {
        float4 w0 = *(const float4*)&ws2[k + 0][cg * 4];
        float4 w1v = *(const float4*)&ws2[k + 1][cg * 4];
        float4 w2v = *(const float4*)&ws2[k + 2][cg * 4];
        float4 w3v = *(const float4*)&ws2[k + 3][cg * 4];
#pragma unroll
        for (int u = 0; u < 4; ++u) {
            float4 xv = *(const float4*)&xs2[ng * 4 + u][k];
            acc[u][0] += xv.x*w0.x + xv.y*w1v.x + xv.z*w2v.x + xv.w*w3v.x;
            acc[u][1] += xv.x*w0.y + xv.y*w1v.y + xv.z*w2v.y + xv.w*w3v.y;
            acc[u][2] += xv.x*w0.z + xv.y*w1v.z + xv.z*w2v.z + xv.w*w3v.z;
            acc[u][3] += xv.x*w0.w + xv.y*w1v.w + xv.z*w2v.w + xv.w*w3v.w;
        }
    }
    __syncthreads();
#pragma unroll
    for (int u = 0; u < 4; ++u) {
        int nl = ng * 4 + u;
        int n = nbase + nl;
#pragma unroll
        for (int j = 0; j < 4; ++j) xs2[nl][cg * 4 + j] = acc[u][j];
        if (n < N_NODES) {
            union { __half2 h[2]; uint2 u2; } pk;
            pk.h[0] = __floats2half2_rn(acc[u][0], acc[u][1]);
            pk.h[1] = __floats2half2_rn(acc[u][2], acc[u][3]);
            *(uint2*)(g_g2h + (size_t)n * C + cg * 4) = pk.u2;
        }
    }
    __syncthreads();
    if (t < NT2) {
        int n = nbase + t;
        if (n < N_NODES) {
            float ts = 0.f, td = 0.f;
#pragma unroll 8
            for (int c = 0; c < C; ++c) {
                float gv = xs2[t][c];
                ts = fmaf(gv, sas[c], ts);
                td = fmaf(gv, sad[c], td);
            }
            g_als2[n] = ts;
            g_ald2[n] = td;
        }
    }
}

// ========== Layer 2 gather: PDL secondary of gemm2K ==========
__global__ void gather2K(const float* __restrict__ b2, float* __restrict__ out) {
    int w = (blockIdx.x * blockDim.x + threadIdx.x) >> 5;
    if (w >= N_NODES) { cudaGridDependencySynchronize(); return; }
    int lane = threadIdx.x & 31;
    int g = lane >> 3, l = lane & 7;
    int d = w;
    int beg = g_off[d], end = g_off[d + 1];   // ancestor data (CSR) — safe pre-sync
    cudaGridDependencySynchronize();          // wait for gemm2K's g2/als2/ald2
    float ald = g_ald2[d];
    float acc[8] = {};
    float s = 0.f;
    int last = end - 1;
    bool feat = (l < 5);
    int fcol = feat ? l * 8 : 0;

    for (int i = beg; i < end; i += 8) {
        int e0 = i + g, e1 = i + g + 4;
        bool v0 = e0 < end, v1 = e1 < end;
        int c0 = v0 ? e0 : last, c1 = v1 ? e1 : last;
        int s0 = (int)g_csr_src[c0];
        int s1 = (int)g_csr_src[c1];
        float a0 = g_als2[s0];
        float a1 = g_als2[s1];
        uint4 r0 = make_uint4(0, 0, 0, 0), r1 = make_uint4(0, 0, 0, 0);
        if (feat) {
            r0 = *(const uint4*)(g_g2h + (size_t)s0 * C + fcol);
            r1 = *(const uint4*)(g_g2h + (size_t)s1 * C + fcol);
        }
        float p0 = v0 ? __expf(lrelu(a0 + ald)) : 0.f;
        float p1 = v1 ? __expf(lrelu(a1 + ald)) : 0.f;
        s += p0 + p1;
        float2 f;
        f = __half22float2(*(__half2*)&r0.x); acc[0] = fmaf(p0, f.x, acc[0]); acc[1] = fmaf(p0, f.y, acc[1]);
        f = __half22float2(*(__half2*)&r0.y); acc[2] = fmaf(p0, f.x, acc[2]); acc[3] = fmaf(p0, f.y, acc[3]);
        f = __half22float2(*(__half2*)&r0.z); acc[4] = fmaf(p0, f.x, acc[4]); acc[5] = fmaf(p0, f.y, acc[5]);
        f = __half22float2(*(__half2*)&r0.w); acc[6] = fmaf(p0, f.x, acc[6]); acc[7] = fmaf(p0, f.y, acc[7]);
        f = __half22float2(*(__half2*)&r1.x); acc[0] = fmaf(p1, f.x, acc[0]); acc[1] = fmaf(p1, f.y, acc[1]);
        f = __half22float2(*(__half2*)&r1.y); acc[2] = fmaf(p1, f.x, acc[2]); acc[3] = fmaf(p1, f.y, acc[3]);
        f = __half22float2(*(__half2*)&r1.z); acc[4] = fmaf(p1, f.x, acc[4]); acc[5] = fmaf(p1, f.y, acc[5]);
        f = __half22float2(*(__half2*)&r1.w); acc[6] = fmaf(p1, f.x, acc[6]); acc[7] = fmaf(p1, f.y, acc[7]);
    }
#pragma unroll
    for (int j = 0; j < 8; ++j) {
        acc[j] += __shfl_xor_sync(0xffffffffu, acc[j], 8);
        acc[j] += __shfl_xor_sync(0xffffffffu, acc[j], 16);
    }
    s += __shfl_xor_sync(0xffffffffu, s, 8);
    s += __shfl_xor_sync(0xffffffffu, s, 16);
    float inv = 1.f / s;

    float v[8];
    float m = -INFINITY;
    if (feat) {
#pragma unroll
        for (int j = 0; j < 8; ++j) {
            v[j] = acc[j] * inv + b2[fcol + j];
            m = fmaxf(m, v[j]);
        }
    }
#pragma unroll
    for (int off = 1; off < 8; off <<= 1)
        m = fmaxf(m, __shfl_xor_sync(0xffffffffu, m, off));
    float es = 0.f;
    if (feat) {
#pragma unroll
        for (int j = 0; j < 8; ++j) es += expf(v[j] - m);
    }
#pragma unroll
    for (int off = 1; off < 8; off <<= 1)
        es += __shfl_xor_sync(0xffffffffu, es, off);
    float lse = logf(es) + m;
    if (g == 0 && feat) {
        float4 o0 = make_float4(v[0] - lse, v[1] - lse, v[2] - lse, v[3] - lse);
        float4 o1 = make_float4(v[4] - lse, v[5] - lse, v[6] - lse, v[7] - lse);
        *(float4*)(out + (size_t)d * C + fcol)     = o0;
        *(float4*)(out + (size_t)d * C + fcol + 4) = o1;
    }
}

// ---- helper: launch with Programmatic Stream Serialization ----
template <typename K, typename... Args>
static void launchPDL(K kernel, dim3 grid, dim3 block, Args... args) {
    cudaLaunchAttribute attr[1];
    attr[0].id = cudaLaunchAttributeProgrammaticStreamSerialization;
    attr[0].val.programmaticStreamSerializationAllowed = 1;
    cudaLaunchConfig_t cfg = {};
    cfg.gridDim = grid;
    cfg.blockDim = block;
    cfg.dynamicSmemBytes = 0;
    cfg.stream = 0;
    cfg.attrs = attr;
    cfg.numAttrs = 1;
    cudaLaunchKernelEx(&cfg, kernel, args...);
}

extern "C" void kernel_launch(void* const* d_in, const int* in_sizes, int n_in,
                              void* d_out, int out_size) {
    const float* x    = (const float*)d_in[0];
    const float* topo = (const float*)d_in[1];
    const int*   ei   = (const int*)  d_in[2];
    const float* W1   = (const float*)d_in[3];
    const float* as1  = (const float*)d_in[4];
    const float* ad1  = (const float*)d_in[5];
    const float* b1   = (const float*)d_in[6];
    const float* W2   = (const float*)d_in[7];
    const float* as2  = (const float*)d_in[8];
    const float* ad2  = (const float*)d_in[9];
    const float* b2   = (const float*)d_in[10];
    float* out = (float*)d_out;

    int E    = in_sizes[2] / 2;
    int Etot = E + N_NODES;

    // fork: gemm1 runs concurrently with the CSR build
    cudaEventRecord(s_evFork, 0);
    cudaStreamWaitEvent(s_side, s_evFork, 0);
    gemm1K<<<(N_NODES + NT1 - 1) / NT1, 256, 0, s_side>>>(x, topo, W1, as1, ad1);
    cudaEventRecord(s_evJoin, s_side);

    // CSR build with PDL between the stages
    histK<<<(Etot + 1023) / 1024, 256>>>(ei, E, Etot);
    launchPDL(scanK, dim3(NB_SCAN), dim3(1024));
    launchPDL(scatterK, dim3((Etot + 1023) / 1024), dim3(256), ei, E, Etot);

    // join, then the dependent chain (PDL on gemm2 and gather2)
    cudaStreamWaitEvent(0, s_evJoin, 0);
    gather1K<<<(N_NODES * 32 + 255) / 256, 256>>>(b1);
    launchPDL(gemm2K, dim3((N_NODES + NT2 - 1) / NT2), dim3(320), W2, as2, ad2);
    launchPDL(gather2K, dim3((N_NODES * 32 + 255) / 256), dim3(256), b2, out);
}